// round 1
// baseline (speedup 1.0000x reference)
#include <cuda_runtime.h>
#include <cuda_bf16.h>
#include <math.h>

// Problem dims
#define B 128
#define S 2048
#define H 512
#define V 32000
#define G 1536            // 3*H
#define NWARP_ATTN 16

// ---------------- scratch (no allocs allowed) ----------------
__device__ float g_gi[B * G];
__device__ float g_gh[B * G];
__device__ float g_hnew[B * H];
__device__ float g_ctx[B * H];
__device__ float g_concat[B * H];
__device__ float g_m[B];
__device__ float g_l[B];

// ---------------- K1: gi / gh gate GEMVs (warp per output) ----------------
// gid < B*G  : gi[b][j] = dot(embedding[idx[b]], w_ih[j]) + b_ih[j]
// gid >= B*G : gh[b][j] = dot(h0[b],            w_hh[j]) + b_hh[j]
__global__ void k_gates(const int* __restrict__ idx,
                        const float* __restrict__ h0,
                        const float* __restrict__ emb,
                        const float* __restrict__ wih,
                        const float* __restrict__ whh,
                        const float* __restrict__ bih,
                        const float* __restrict__ bhh) {
    int lane = threadIdx.x & 31;
    int gid = blockIdx.x * 8 + (threadIdx.x >> 5);
    int which = gid / (B * G);
    int rem = gid - which * (B * G);
    int b = rem / G;
    int j = rem - b * G;

    const float* src = which ? (h0 + b * H) : (emb + (size_t)idx[b] * H);
    const float* w = (which ? whh : wih) + (size_t)j * H;

    float sum = 0.f;
#pragma unroll
    for (int i = 0; i < 16; i++) {
        int k = lane + 32 * i;
        sum += src[k] * w[k];
    }
#pragma unroll
    for (int o = 16; o > 0; o >>= 1)
        sum += __shfl_xor_sync(0xffffffffu, sum, o);

    if (lane == 0) {
        float bias = which ? bhh[j] : bih[j];
        (which ? g_gh : g_gi)[b * G + j] = sum + bias;
    }
}

// ---------------- K2: GRU elementwise ----------------
__global__ void k_gru(const float* __restrict__ h0, float* __restrict__ out_h) {
    int t = blockIdx.x * blockDim.x + threadIdx.x;   // t < B*H
    int b = t >> 9;
    int hh = t & (H - 1);
    const float* gi = g_gi + b * G;
    const float* gh = g_gh + b * G;
    float gr = gi[hh] + gh[hh];
    float gz = gi[H + hh] + gh[H + hh];
    float r = 1.f / (1.f + __expf(-gr));
    float z = 1.f / (1.f + __expf(-gz));
    float n = tanhf(gi[2 * H + hh] + r * gh[2 * H + hh]);
    float hp = h0[t];
    float hn = (1.f - z) * n + z * hp;
    g_hnew[t] = hn;
    out_h[t] = hn;
}

// ---------------- K3: fused energies + online softmax + context ----------------
// one CTA per batch row, 16 warps; warp-private (m,l,ctx) accumulators.
// writes RAW energies to attn_raw (normalized later), normalized context to g_ctx.
__global__ __launch_bounds__(512, 1) void k_attn(const float* __restrict__ enc,
                                                 float* __restrict__ attn_raw) {
    int b = blockIdx.x;
    int lane = threadIdx.x & 31;
    int warp = threadIdx.x >> 5;

    const float* hrow = g_hnew + b * H;
    float hreg[16];
#pragma unroll
    for (int i = 0; i < 16; i++) hreg[i] = hrow[lane + 32 * i];

    float m = -1e30f, l = 0.f;
    float ctx[16];
#pragma unroll
    for (int i = 0; i < 16; i++) ctx[i] = 0.f;

    const float* encb = enc + (size_t)b * S * H;
    for (int s = warp; s < S; s += NWARP_ATTN) {
        const float* er = encb + (size_t)s * H;
        float ev[16];
        float dot = 0.f;
#pragma unroll
        for (int i = 0; i < 16; i++) ev[i] = er[lane + 32 * i];
#pragma unroll
        for (int i = 0; i < 16; i++) dot += hreg[i] * ev[i];
#pragma unroll
        for (int o = 16; o > 0; o >>= 1)
            dot += __shfl_xor_sync(0xffffffffu, dot, o);

        if (lane == 0) attn_raw[b * S + s] = dot;

        float mn = fmaxf(m, dot);
        float scale = __expf(m - mn);
        float p = __expf(dot - mn);
        l = l * scale + p;
#pragma unroll
        for (int i = 0; i < 16; i++) ctx[i] = ctx[i] * scale + p * ev[i];
        m = mn;
    }

    __shared__ float sm_m[NWARP_ATTN];
    __shared__ float sm_l[NWARP_ATTN];
    __shared__ float sm_ctx[NWARP_ATTN][H];
#pragma unroll
    for (int i = 0; i < 16; i++) sm_ctx[warp][lane + 32 * i] = ctx[i];
    if (lane == 0) { sm_m[warp] = m; sm_l[warp] = l; }
    __syncthreads();

    int t = threadIdx.x;  // 0..511 -> h index
    float mg = -1e30f;
#pragma unroll
    for (int w = 0; w < NWARP_ATTN; w++) mg = fmaxf(mg, sm_m[w]);
    float lg = 0.f, c = 0.f;
#pragma unroll
    for (int w = 0; w < NWARP_ATTN; w++) {
        float sc = __expf(sm_m[w] - mg);
        lg += sc * sm_l[w];
        c += sc * sm_ctx[w][t];
    }
    g_ctx[b * H + t] = c / lg;
    if (t == 0) { g_m[b] = mg; g_l[b] = lg; }
}

// ---------------- K4: normalize attention in-place ----------------
__global__ void k_attn_norm(float* __restrict__ attn) {
    int t = blockIdx.x * blockDim.x + threadIdx.x;   // t < B*S
    int b = t >> 11;
    attn[t] = __expf(attn[t] - g_m[b]) / g_l[b];
}

// ---------------- K5: concat GEMV + tanh (warp per output) ----------------
__global__ void k_concat(const float* __restrict__ Wc,
                         const float* __restrict__ bc) {
    int lane = threadIdx.x & 31;
    int gid = blockIdx.x * 8 + (threadIdx.x >> 5);   // gid < B*H
    int b = gid >> 9;
    int j = gid & (H - 1);
    const float* wrow = Wc + (size_t)j * (2 * H);
    const float* hn = g_hnew + b * H;
    const float* cx = g_ctx + b * H;
    float sum = 0.f;
#pragma unroll
    for (int i = 0; i < 16; i++) {
        int k = lane + 32 * i;
        sum += hn[k] * wrow[k];
    }
#pragma unroll
    for (int i = 0; i < 16; i++) {
        int k = lane + 32 * i;
        sum += cx[k] * wrow[H + k];
    }
#pragma unroll
    for (int o = 16; o > 0; o >>= 1)
        sum += __shfl_xor_sync(0xffffffffu, sum, o);
    if (lane == 0) g_concat[b * H + j] = tanhf(sum + bc[j]);
}

// ---------------- K6: output GEMM 128(B) x 32000(V) x 512(K), fp32 tiled ----------------
// CTA tile: 128b x 128n, BK=16, 256 threads, 8x8 per thread.
#define BK 16
__global__ __launch_bounds__(256, 2) void k_out(const float* __restrict__ Wout,
                                                const float* __restrict__ bout,
                                                float* __restrict__ out) {
    __shared__ float As[BK][129];   // [k][b], padded
    __shared__ float Bs[BK][129];   // [k][n], padded
    int n0 = blockIdx.x * 128;
    int t = threadIdx.x;
    int tx = t & 15;        // n group
    int ty = t >> 4;        // b group

    float acc[8][8];
#pragma unroll
    for (int i = 0; i < 8; i++)
#pragma unroll
        for (int j = 0; j < 8; j++) acc[i][j] = 0.f;

    for (int k0 = 0; k0 < H; k0 += BK) {
#pragma unroll
        for (int q = t; q < 512; q += 256) {
            int bb = q >> 2;
            int kk = (q & 3) * 4;
            float4 v = *(const float4*)(g_concat + bb * H + k0 + kk);
            As[kk + 0][bb] = v.x; As[kk + 1][bb] = v.y;
            As[kk + 2][bb] = v.z; As[kk + 3][bb] = v.w;
        }
#pragma unroll
        for (int q = t; q < 512; q += 256) {
            int nn = q >> 2;
            int kk = (q & 3) * 4;
            float4 v = *(const float4*)(Wout + (size_t)(n0 + nn) * H + k0 + kk);
            Bs[kk + 0][nn] = v.x; Bs[kk + 1][nn] = v.y;
            Bs[kk + 2][nn] = v.z; Bs[kk + 3][nn] = v.w;
        }
        __syncthreads();
#pragma unroll
        for (int k = 0; k < BK; k++) {
            float rb[8], rn[8];
#pragma unroll
            for (int i = 0; i < 8; i++) rb[i] = As[k][ty + 16 * i];
#pragma unroll
            for (int j = 0; j < 8; j++) rn[j] = Bs[k][tx + 16 * j];
#pragma unroll
            for (int i = 0; i < 8; i++)
#pragma unroll
                for (int j = 0; j < 8; j++) acc[i][j] += rb[i] * rn[j];
        }
        __syncthreads();
    }

#pragma unroll
    for (int j = 0; j < 8; j++) {
        int n = n0 + tx + 16 * j;
        float bo = bout[n];
#pragma unroll
        for (int i = 0; i < 8; i++) {
            int bb = ty + 16 * i;
            out[(size_t)bb * V + n] = acc[i][j] + bo;
        }
    }
}

// ---------------- launch ----------------
extern "C" void kernel_launch(void* const* d_in, const int* in_sizes, int n_in,
                              void* d_out, int out_size) {
    const int*   idx  = (const int*)  d_in[0];
    const float* h0   = (const float*)d_in[1];
    const float* enc  = (const float*)d_in[2];
    const float* emb  = (const float*)d_in[3];
    const float* wih  = (const float*)d_in[4];
    const float* whh  = (const float*)d_in[5];
    const float* bih  = (const float*)d_in[6];
    const float* bhh  = (const float*)d_in[7];
    const float* Wc   = (const float*)d_in[8];
    const float* bc   = (const float*)d_in[9];
    const float* Wout = (const float*)d_in[10];
    const float* bout = (const float*)d_in[11];

    float* out_logits = (float*)d_out;                 // B*V
    float* out_h      = out_logits + (size_t)B * V;    // B*H
    float* out_attn   = out_h + (size_t)B * H;         // B*S

    // K1: 2*B*G dots, 8 warps/CTA
    k_gates<<<(2 * B * G) / 8, 256>>>(idx, h0, emb, wih, whh, bih, bhh);
    // K2: GRU update
    k_gru<<<(B * H) / 256, 256>>>(h0, out_h);
    // K3: fused attention (raw energies into out_attn)
    k_attn<<<B, 512>>>(enc, out_attn);
    // K4: normalize attention
    k_attn_norm<<<(B * S) / 256, 256>>>(out_attn);
    // K5: concat projection + tanh
    k_concat<<<(B * H) / 8, 256>>>(Wc, bc);
    // K6: output GEMM
    k_out<<<V / 128, 256>>>(Wout, bout, out_logits);
}

// round 3
// speedup vs baseline: 1.2872x; 1.2872x over previous
#include <cuda_runtime.h>
#include <cuda_bf16.h>
#include <cstdint>
#include <math.h>

// Problem dims
#define B 128
#define S 2048
#define H 512
#define V 32000
#define G 1536            // 3*H
#define NWARP_ATTN 16

// ---------------- scratch (no allocs allowed) ----------------
__device__ float g_gi[B * G];
__device__ float g_gh[B * G];
__device__ float g_hcat[B * 1024];     // [h_new | context] per row
__device__ float g_concat[B * H];

// =================== HMMA GEMM: C = act(A @ W^T + bias) ===================
// A: 128 x K fp32 (optionally row-gathered via gidx), W: N x K fp32 row-major.
// 3-term bf16 split for near-fp32 accuracy: A*W ~= Ah*Wh + Ah*Wl + Al*Wh.
// CTA tile 128(M) x 128(N), K-tile 64. 8 warps: 2(M) x 4(N), warp tile 64x32.

#define KT 64
#define ASTRIDE 72   // bf16 elements per row in smem (64 + 8 pad) -> conflict-free frags
#define TILE_ELEMS (128 * ASTRIDE)
#define GEMM_SMEM (4 * TILE_ELEMS * 2)   // Ah, Al, Wh, Wl  (73728 B)

__device__ __forceinline__ void mma16816(float* c, const uint32_t* a, const uint32_t* b) {
    asm volatile(
        "mma.sync.aligned.m16n8k16.row.col.f32.bf16.bf16.f32 "
        "{%0,%1,%2,%3}, {%4,%5,%6,%7}, {%8,%9}, {%0,%1,%2,%3};"
        : "+f"(c[0]), "+f"(c[1]), "+f"(c[2]), "+f"(c[3])
        : "r"(a[0]), "r"(a[1]), "r"(a[2]), "r"(a[3]), "r"(b[0]), "r"(b[1]));
}

// split fp32 -> (hi, lo) bf16 pair packed two-at-a-time; store 4 consecutive k.
__device__ __forceinline__ void cvt_store4(__nv_bfloat16* hi, __nv_bfloat16* lo,
                                           int base, float4 v) {
    float f[4] = {v.x, v.y, v.z, v.w};
#pragma unroll
    for (int p = 0; p < 2; p++) {
        float a0 = f[2 * p], a1 = f[2 * p + 1];
        __nv_bfloat16 h0 = __float2bfloat16(a0);
        __nv_bfloat16 h1 = __float2bfloat16(a1);
        __nv_bfloat16 l0 = __float2bfloat16(a0 - __bfloat162float(h0));
        __nv_bfloat16 l1 = __float2bfloat16(a1 - __bfloat162float(h1));
        __nv_bfloat162 th; th.x = h0; th.y = h1;
        __nv_bfloat162 tl; tl.x = l0; tl.y = l1;
        *(__nv_bfloat162*)(hi + base + 2 * p) = th;
        *(__nv_bfloat162*)(lo + base + 2 * p) = tl;
    }
}

__global__ __launch_bounds__(256, 1) void k_gemm(
    const float* Aa, const float* Ab, const int* gia, const int* gib,
    const float* Wa, const float* Wb, const float* ba_, const float* bb_,
    float* Ca, float* Cb, int kTiles, int ldc, int act) {
    extern __shared__ __nv_bfloat16 sm[];
    __nv_bfloat16* Ah = sm;
    __nv_bfloat16* Al = sm + TILE_ELEMS;
    __nv_bfloat16* Wh = sm + 2 * TILE_ELEMS;
    __nv_bfloat16* Wl = sm + 3 * TILE_ELEMS;

    int tid = threadIdx.x;
    int wid = tid >> 5;
    int lane = tid & 31;
    int wm = (wid >> 2) * 64;       // warp M offset (0 / 64)
    int wn = (wid & 3) * 32;        // warp N offset (0/32/64/96)

    int set = blockIdx.y;
    const float* A = set ? Ab : Aa;
    const int* gidx = set ? gib : gia;
    const float* W = set ? Wb : Wa;
    const float* bias = set ? bb_ : ba_;
    float* C = set ? Cb : Ca;

    int n0 = blockIdx.x * 128;
    int K = kTiles * KT;

    float acc[4][4][4];
#pragma unroll
    for (int i = 0; i < 4; i++)
#pragma unroll
        for (int j = 0; j < 4; j++)
#pragma unroll
            for (int c = 0; c < 4; c++) acc[i][j][c] = 0.f;

    for (int kt = 0; kt < kTiles; kt++) {
        int k0 = kt * KT;
        // ---- load + split A tile (128 x 64) ----
#pragma unroll
        for (int i = tid; i < 2048; i += 256) {
            int row = i >> 4;
            int kq = (i & 15) << 2;
            int ar = gidx ? gidx[row] : row;
            float4 v = *(const float4*)(A + (size_t)ar * K + k0 + kq);
            cvt_store4(Ah, Al, row * ASTRIDE + kq, v);
        }
        // ---- load + split W tile (128 x 64) ----
#pragma unroll
        for (int i = tid; i < 2048; i += 256) {
            int row = i >> 4;
            int kq = (i & 15) << 2;
            float4 v = *(const float4*)(W + (size_t)(n0 + row) * K + k0 + kq);
            cvt_store4(Wh, Wl, row * ASTRIDE + kq, v);
        }
        __syncthreads();

#pragma unroll
        for (int ks = 0; ks < 4; ks++) {
            int kb = ks * 16 + (lane & 3) * 2;
            uint32_t ah[4][4], al[4][4], wh[4][2], wl[4][2];
#pragma unroll
            for (int mt = 0; mt < 4; mt++) {
                int r = wm + mt * 16 + (lane >> 2);
                ah[mt][0] = *(const uint32_t*)(Ah + r * ASTRIDE + kb);
                ah[mt][1] = *(const uint32_t*)(Ah + (r + 8) * ASTRIDE + kb);
                ah[mt][2] = *(const uint32_t*)(Ah + r * ASTRIDE + kb + 8);
                ah[mt][3] = *(const uint32_t*)(Ah + (r + 8) * ASTRIDE + kb + 8);
                al[mt][0] = *(const uint32_t*)(Al + r * ASTRIDE + kb);
                al[mt][1] = *(const uint32_t*)(Al + (r + 8) * ASTRIDE + kb);
                al[mt][2] = *(const uint32_t*)(Al + r * ASTRIDE + kb + 8);
                al[mt][3] = *(const uint32_t*)(Al + (r + 8) * ASTRIDE + kb + 8);
            }
#pragma unroll
            for (int nt = 0; nt < 4; nt++) {
                int n = wn + nt * 8 + (lane >> 2);
                wh[nt][0] = *(const uint32_t*)(Wh + n * ASTRIDE + kb);
                wh[nt][1] = *(const uint32_t*)(Wh + n * ASTRIDE + kb + 8);
                wl[nt][0] = *(const uint32_t*)(Wl + n * ASTRIDE + kb);
                wl[nt][1] = *(const uint32_t*)(Wl + n * ASTRIDE + kb + 8);
            }
#pragma unroll
            for (int mt = 0; mt < 4; mt++)
#pragma unroll
                for (int nt = 0; nt < 4; nt++) {
                    mma16816(acc[mt][nt], ah[mt], wh[nt]);
                    mma16816(acc[mt][nt], ah[mt], wl[nt]);
                    mma16816(acc[mt][nt], al[mt], wh[nt]);
                }
        }
        __syncthreads();
    }

    // ---- epilogue: bias + optional tanh, direct stores (float2 per quad-lane) ----
#pragma unroll
    for (int mt = 0; mt < 4; mt++) {
        int r0 = wm + mt * 16 + (lane >> 2);
#pragma unroll
        for (int nt = 0; nt < 4; nt++) {
            int col = n0 + wn + nt * 8 + (lane & 3) * 2;
            float b0 = bias[col], b1 = bias[col + 1];
            float v0 = acc[mt][nt][0] + b0;
            float v1 = acc[mt][nt][1] + b1;
            float v2 = acc[mt][nt][2] + b0;
            float v3 = acc[mt][nt][3] + b1;
            if (act) { v0 = tanhf(v0); v1 = tanhf(v1); v2 = tanhf(v2); v3 = tanhf(v3); }
            *(float2*)(C + (size_t)r0 * ldc + col) = make_float2(v0, v1);
            *(float2*)(C + (size_t)(r0 + 8) * ldc + col) = make_float2(v2, v3);
        }
    }
}

// ---------------- GRU elementwise (writes h into g_hcat[:, :512] and out_h) ----------------
__global__ void k_gru(const float* __restrict__ h0, float* __restrict__ out_h) {
    int t = blockIdx.x * blockDim.x + threadIdx.x;   // t < B*H
    int b = t >> 9;
    int hh = t & (H - 1);
    const float* gi = g_gi + b * G;
    const float* gh = g_gh + b * G;
    float gr = gi[hh] + gh[hh];
    float gz = gi[H + hh] + gh[H + hh];
    float r = 1.f / (1.f + __expf(-gr));
    float z = 1.f / (1.f + __expf(-gz));
    float n = tanhf(gi[2 * H + hh] + r * gh[2 * H + hh]);
    float hp = h0[t];
    float hn = (1.f - z) * n + z * hp;
    g_hcat[b * 1024 + hh] = hn;
    out_h[t] = hn;
}

// ---------------- fused energies + online softmax + context + normalize ----------------
__global__ __launch_bounds__(512, 1) void k_attn(const float* __restrict__ enc,
                                                 float* __restrict__ attn_out) {
    int b = blockIdx.x;
    int lane = threadIdx.x & 31;
    int warp = threadIdx.x >> 5;

    const float4* hrow = (const float4*)(g_hcat + b * 1024);
    float4 hreg[4];
#pragma unroll
    for (int i = 0; i < 4; i++) hreg[i] = hrow[lane + 32 * i];

    float m = -1e30f, l = 0.f;
    float4 ctx[4];
#pragma unroll
    for (int i = 0; i < 4; i++) ctx[i] = make_float4(0.f, 0.f, 0.f, 0.f);

    const float* encb = enc + (size_t)b * S * H;
    for (int s = warp; s < S; s += NWARP_ATTN) {
        const float4* er = (const float4*)(encb + (size_t)s * H);
        float4 ev[4];
#pragma unroll
        for (int i = 0; i < 4; i++) ev[i] = er[lane + 32 * i];
        float dot = 0.f;
#pragma unroll
        for (int i = 0; i < 4; i++)
            dot += hreg[i].x * ev[i].x + hreg[i].y * ev[i].y +
                   hreg[i].z * ev[i].z + hreg[i].w * ev[i].w;
#pragma unroll
        for (int o = 16; o > 0; o >>= 1)
            dot += __shfl_xor_sync(0xffffffffu, dot, o);

        if (lane == 0) attn_out[b * S + s] = dot;   // raw energy, normalized below

        float mn = fmaxf(m, dot);
        float scale = __expf(m - mn);
        float p = __expf(dot - mn);
        l = l * scale + p;
#pragma unroll
        for (int i = 0; i < 4; i++) {
            ctx[i].x = ctx[i].x * scale + p * ev[i].x;
            ctx[i].y = ctx[i].y * scale + p * ev[i].y;
            ctx[i].z = ctx[i].z * scale + p * ev[i].z;
            ctx[i].w = ctx[i].w * scale + p * ev[i].w;
        }
        m = mn;
    }

    __shared__ float sm_m[NWARP_ATTN];
    __shared__ float sm_l[NWARP_ATTN];
    __shared__ float sm_ctx[NWARP_ATTN][H];
#pragma unroll
    for (int i = 0; i < 4; i++)
        ((float4*)sm_ctx[warp])[lane + 32 * i] = ctx[i];
    if (lane == 0) { sm_m[warp] = m; sm_l[warp] = l; }
    __syncthreads();

    int t = threadIdx.x;  // 0..511 -> h index
    float mg = -1e30f;
#pragma unroll
    for (int w = 0; w < NWARP_ATTN; w++) mg = fmaxf(mg, sm_m[w]);
    float lg = 0.f, c = 0.f;
#pragma unroll
    for (int w = 0; w < NWARP_ATTN; w++) {
        float sc = __expf(sm_m[w] - mg);
        lg += sc * sm_l[w];
        c += sc * sm_ctx[w][t];
    }
    float inv = 1.f / lg;
    g_hcat[b * 1024 + 512 + t] = c * inv;

    // normalize the raw energies in place (L2-hot, written by this CTA)
    for (int s = threadIdx.x; s < S; s += 512)
        attn_out[b * S + s] = __expf(attn_out[b * S + s] - mg) * inv;
}

// ---------------- launch ----------------
extern "C" void kernel_launch(void* const* d_in, const int* in_sizes, int n_in,
                              void* d_out, int out_size) {
    const int*   idx  = (const int*)  d_in[0];
    const float* h0   = (const float*)d_in[1];
    const float* enc  = (const float*)d_in[2];
    const float* emb  = (const float*)d_in[3];
    const float* wih  = (const float*)d_in[4];
    const float* whh  = (const float*)d_in[5];
    const float* bih  = (const float*)d_in[6];
    const float* bhh  = (const float*)d_in[7];
    const float* Wc   = (const float*)d_in[8];
    const float* bc   = (const float*)d_in[9];
    const float* Wout = (const float*)d_in[10];
    const float* bout = (const float*)d_in[11];

    float* out_logits = (float*)d_out;                 // B*V
    float* out_h      = out_logits + (size_t)B * V;    // B*H
    float* out_attn   = out_h + (size_t)B * H;         // B*S

    float* gi_p; cudaGetSymbolAddress((void**)&gi_p, g_gi);
    float* gh_p; cudaGetSymbolAddress((void**)&gh_p, g_gh);
    float* hc_p; cudaGetSymbolAddress((void**)&hc_p, g_hcat);
    float* cc_p; cudaGetSymbolAddress((void**)&cc_p, g_concat);

    cudaFuncSetAttribute(k_gemm, cudaFuncAttributeMaxDynamicSharedMemorySize, GEMM_SMEM);

    // 1) GRU gate GEMMs: gi = emb[idx] @ wih^T + bih ; gh = h0 @ whh^T + bhh
    k_gemm<<<dim3(G / 128, 2), 256, GEMM_SMEM>>>(
        emb, h0, idx, (const int*)nullptr,
        wih, whh, bih, bhh, gi_p, gh_p,
        H / KT, G, 0);
    // 2) GRU elementwise
    k_gru<<<(B * H) / 256, 256>>>(h0, out_h);
    // 3) fused attention (context into g_hcat[:,512:], normalized attn out)
    k_attn<<<B, 512>>>(enc, out_attn);
    // 4) concat projection + tanh: g_concat = tanh(g_hcat @ Wc^T + bc)
    k_gemm<<<dim3(H / 128, 1), GEMM_SMEM ? 256 : 256, GEMM_SMEM>>>(
        hc_p, hc_p, (const int*)nullptr, (const int*)nullptr,
        Wc, Wc, bc, bc, cc_p, cc_p,
        1024 / KT, H, 1);
    // 5) output GEMM: logits = g_concat @ Wout^T + bout
    k_gemm<<<dim3(V / 128, 1), 256, GEMM_SMEM>>>(
        cc_p, cc_p, (const int*)nullptr, (const int*)nullptr,
        Wout, Wout, bout, bout, out_logits, out_logits,
        H / KT, V, 0);
}

// round 4
// speedup vs baseline: 1.7738x; 1.3780x over previous
#include <cuda_runtime.h>
#include <cuda_bf16.h>
#include <cstdint>
#include <math.h>

// Problem dims
#define B 128
#define S 2048
#define H 512
#define V 32000
#define G 1536            // 3*H
#define NWARP_ATTN 16
#define CH_G 4            // k-split chunks for gates GEMM (K=512 -> 128/chunk)
#define CH_C 8            // k-split chunks for concat GEMM (K=1024 -> 128/chunk)

// ---------------- scratch (no allocs allowed) ----------------
__device__ float g_gpart[2 * CH_G * B * G];   // gates partials [set][chunk][b][j]
__device__ float g_cpart[CH_C * B * H];       // concat partials [chunk][b][j]
__device__ float g_hcat[B * 1024];            // [h_new | context] per row
__device__ float g_concat[B * H];

// =================== HMMA GEMM: C = act(A @ W^T + bias) ===================
// 3-term bf16 split: A*W ~= Ah*Wh + Ah*Wl + Al*Wh  (err ~ Al*Wl ~ 4e-6 rel)
// CTA tile 128(M) x 128(N), K-tile 64. 8 warps: 2(M) x 4(N), warp tile 64x32.
// blockIdx.z = k-chunk (split-K partial mode when partial != 0).

#define KT 64
#define ASTRIDE 72   // bf16/row in smem (64 + 8 pad) -> conflict-free frags
#define TILE_ELEMS (128 * ASTRIDE)
#define GEMM_SMEM (4 * TILE_ELEMS * 2)   // Ah, Al, Wh, Wl (73728 B)

__device__ __forceinline__ void mma16816(float* c, const uint32_t* a, const uint32_t* b) {
    asm volatile(
        "mma.sync.aligned.m16n8k16.row.col.f32.bf16.bf16.f32 "
        "{%0,%1,%2,%3}, {%4,%5,%6,%7}, {%8,%9}, {%0,%1,%2,%3};"
        : "+f"(c[0]), "+f"(c[1]), "+f"(c[2]), "+f"(c[3])
        : "r"(a[0]), "r"(a[1]), "r"(a[2]), "r"(a[3]), "r"(b[0]), "r"(b[1]));
}

__device__ __forceinline__ void cvt_store4(__nv_bfloat16* hi, __nv_bfloat16* lo,
                                           int base, float4 v) {
    float f[4] = {v.x, v.y, v.z, v.w};
#pragma unroll
    for (int p = 0; p < 2; p++) {
        float a0 = f[2 * p], a1 = f[2 * p + 1];
        __nv_bfloat16 h0 = __float2bfloat16(a0);
        __nv_bfloat16 h1 = __float2bfloat16(a1);
        __nv_bfloat16 l0 = __float2bfloat16(a0 - __bfloat162float(h0));
        __nv_bfloat16 l1 = __float2bfloat16(a1 - __bfloat162float(h1));
        __nv_bfloat162 th; th.x = h0; th.y = h1;
        __nv_bfloat162 tl; tl.x = l0; tl.y = l1;
        *(__nv_bfloat162*)(hi + base + 2 * p) = th;
        *(__nv_bfloat162*)(lo + base + 2 * p) = tl;
    }
}

__global__ __launch_bounds__(256, 1) void k_gemm(
    const float* Aa, const float* Ab, const int* gia, const int* gib,
    const float* Wa, const float* Wb, const float* ba_, const float* bb_,
    float* Ca, float* Cb, int K, int ldc, int act,
    int tilesPerChunk, int partial) {
    extern __shared__ __nv_bfloat16 sm[];
    __nv_bfloat16* Ah = sm;
    __nv_bfloat16* Al = sm + TILE_ELEMS;
    __nv_bfloat16* Wh = sm + 2 * TILE_ELEMS;
    __nv_bfloat16* Wl = sm + 3 * TILE_ELEMS;

    int tid = threadIdx.x;
    int wid = tid >> 5;
    int lane = tid & 31;
    int wm = (wid >> 2) * 64;
    int wn = (wid & 3) * 32;

    int set = blockIdx.y;
    const float* A = set ? Ab : Aa;
    const int* gidx = set ? gib : gia;
    const float* W = set ? Wb : Wa;
    const float* bias = set ? bb_ : ba_;
    float* C = set ? Cb : Ca;
    if (partial) C += (size_t)blockIdx.z * 128 * ldc;   // per-chunk partial slab

    int n0 = blockIdx.x * 128;
    int ktBase = blockIdx.z * tilesPerChunk;

    // per-thread load coords (8 float4 per tile each for A and W)
    int lrow[8], lkq[8], larow[8];
#pragma unroll
    for (int ii = 0; ii < 8; ii++) {
        int q = tid + ii * 256;
        lrow[ii] = q >> 4;
        lkq[ii] = (q & 15) << 2;
        larow[ii] = gidx ? gidx[lrow[ii]] : lrow[ii];
    }

    float acc[4][4][4];
#pragma unroll
    for (int i = 0; i < 4; i++)
#pragma unroll
        for (int j = 0; j < 4; j++)
#pragma unroll
            for (int c = 0; c < 4; c++) acc[i][j][c] = 0.f;

    // prologue: prefetch tile 0
    float4 pa[8], pw[8];
    {
        int k0 = ktBase * KT;
#pragma unroll
        for (int ii = 0; ii < 8; ii++) {
            pa[ii] = *(const float4*)(A + (size_t)larow[ii] * K + k0 + lkq[ii]);
            pw[ii] = *(const float4*)(W + (size_t)(n0 + lrow[ii]) * K + k0 + lkq[ii]);
        }
    }

    for (int kt = 0; kt < tilesPerChunk; kt++) {
        // commit prefetched tile to smem (with bf16 hi/lo split)
#pragma unroll
        for (int ii = 0; ii < 8; ii++) {
            cvt_store4(Ah, Al, lrow[ii] * ASTRIDE + lkq[ii], pa[ii]);
            cvt_store4(Wh, Wl, lrow[ii] * ASTRIDE + lkq[ii], pw[ii]);
        }
        __syncthreads();

        // prefetch next tile (overlaps MMA below)
        if (kt + 1 < tilesPerChunk) {
            int k0 = (ktBase + kt + 1) * KT;
#pragma unroll
            for (int ii = 0; ii < 8; ii++) {
                pa[ii] = *(const float4*)(A + (size_t)larow[ii] * K + k0 + lkq[ii]);
                pw[ii] = *(const float4*)(W + (size_t)(n0 + lrow[ii]) * K + k0 + lkq[ii]);
            }
        }

#pragma unroll
        for (int ks = 0; ks < 4; ks++) {
            int kb = ks * 16 + (lane & 3) * 2;
            uint32_t ah[4][4], al[4][4], wh[4][2], wl[4][2];
#pragma unroll
            for (int mt = 0; mt < 4; mt++) {
                int r = wm + mt * 16 + (lane >> 2);
                ah[mt][0] = *(const uint32_t*)(Ah + r * ASTRIDE + kb);
                ah[mt][1] = *(const uint32_t*)(Ah + (r + 8) * ASTRIDE + kb);
                ah[mt][2] = *(const uint32_t*)(Ah + r * ASTRIDE + kb + 8);
                ah[mt][3] = *(const uint32_t*)(Ah + (r + 8) * ASTRIDE + kb + 8);
                al[mt][0] = *(const uint32_t*)(Al + r * ASTRIDE + kb);
                al[mt][1] = *(const uint32_t*)(Al + (r + 8) * ASTRIDE + kb);
                al[mt][2] = *(const uint32_t*)(Al + r * ASTRIDE + kb + 8);
                al[mt][3] = *(const uint32_t*)(Al + (r + 8) * ASTRIDE + kb + 8);
            }
#pragma unroll
            for (int nt = 0; nt < 4; nt++) {
                int n = wn + nt * 8 + (lane >> 2);
                wh[nt][0] = *(const uint32_t*)(Wh + n * ASTRIDE + kb);
                wh[nt][1] = *(const uint32_t*)(Wh + n * ASTRIDE + kb + 8);
                wl[nt][0] = *(const uint32_t*)(Wl + n * ASTRIDE + kb);
                wl[nt][1] = *(const uint32_t*)(Wl + n * ASTRIDE + kb + 8);
            }
#pragma unroll
            for (int mt = 0; mt < 4; mt++)
#pragma unroll
                for (int nt = 0; nt < 4; nt++) {
                    mma16816(acc[mt][nt], ah[mt], wh[nt]);
                    mma16816(acc[mt][nt], ah[mt], wl[nt]);
                    mma16816(acc[mt][nt], al[mt], wh[nt]);
                }
        }
        __syncthreads();
    }

    // ---- epilogue ----
#pragma unroll
    for (int mt = 0; mt < 4; mt++) {
        int r0 = wm + mt * 16 + (lane >> 2);
#pragma unroll
        for (int nt = 0; nt < 4; nt++) {
            int col = n0 + wn + nt * 8 + (lane & 3) * 2;
            float v0 = acc[mt][nt][0];
            float v1 = acc[mt][nt][1];
            float v2 = acc[mt][nt][2];
            float v3 = acc[mt][nt][3];
            if (!partial) {
                float b0 = bias[col], b1 = bias[col + 1];
                v0 += b0; v1 += b1; v2 += b0; v3 += b1;
                if (act) { v0 = tanhf(v0); v1 = tanhf(v1); v2 = tanhf(v2); v3 = tanhf(v3); }
            }
            *(float2*)(C + (size_t)r0 * ldc + col) = make_float2(v0, v1);
            *(float2*)(C + (size_t)(r0 + 8) * ldc + col) = make_float2(v2, v3);
        }
    }
}

// ---------------- GRU elementwise + gates split-K reduction ----------------
__global__ void k_gru(const float* __restrict__ h0,
                      const float* __restrict__ bih, const float* __restrict__ bhh,
                      float* __restrict__ out_h) {
    int t = blockIdx.x * blockDim.x + threadIdx.x;   // t < B*H
    int b = t >> 9;
    int hh = t & (H - 1);
    float gir = bih[hh],       giz = bih[H + hh],       gin = bih[2 * H + hh];
    float ghr = bhh[hh],       ghz = bhh[H + hh],       ghn = bhh[2 * H + hh];
#pragma unroll
    for (int c = 0; c < CH_G; c++) {
        const float* p = g_gpart + ((size_t)c * B + b) * G;
        gir += p[hh]; giz += p[H + hh]; gin += p[2 * H + hh];
        const float* q = g_gpart + ((size_t)(CH_G + c) * B + b) * G;
        ghr += q[hh]; ghz += q[H + hh]; ghn += q[2 * H + hh];
    }
    float r = 1.f / (1.f + __expf(-(gir + ghr)));
    float z = 1.f / (1.f + __expf(-(giz + ghz)));
    float n = tanhf(gin + r * ghn);
    float hp = h0[t];
    float hn = (1.f - z) * n + z * hp;
    g_hcat[b * 1024 + hh] = hn;
    out_h[t] = hn;
}

// ---------------- concat split-K reduction + bias + tanh ----------------
__global__ void k_cfin(const float* __restrict__ bc) {
    int t = blockIdx.x * blockDim.x + threadIdx.x;   // t < B*H
    int b = t >> 9;
    int j = t & (H - 1);
    float sum = bc[j];
#pragma unroll
    for (int c = 0; c < CH_C; c++)
        sum += g_cpart[((size_t)c * B + b) * H + j];
    g_concat[t] = tanhf(sum);
}

// ---------------- fused energies + online softmax + context + normalize ----------------
__global__ __launch_bounds__(512, 1) void k_attn(const float* __restrict__ enc,
                                                 float* __restrict__ attn_out) {
    int b = blockIdx.x;
    int lane = threadIdx.x & 31;
    int warp = threadIdx.x >> 5;

    const float4* hrow = (const float4*)(g_hcat + b * 1024);
    float4 hreg[4];
#pragma unroll
    for (int i = 0; i < 4; i++) hreg[i] = hrow[lane + 32 * i];

    float m = -1e30f, l = 0.f;
    float4 ctx[4];
#pragma unroll
    for (int i = 0; i < 4; i++) ctx[i] = make_float4(0.f, 0.f, 0.f, 0.f);

    const float* encb = enc + (size_t)b * S * H;
    for (int s = warp; s < S; s += NWARP_ATTN) {
        const float4* er = (const float4*)(encb + (size_t)s * H);
        float4 ev[4];
#pragma unroll
        for (int i = 0; i < 4; i++) ev[i] = er[lane + 32 * i];
        float dot = 0.f;
#pragma unroll
        for (int i = 0; i < 4; i++)
            dot += hreg[i].x * ev[i].x + hreg[i].y * ev[i].y +
                   hreg[i].z * ev[i].z + hreg[i].w * ev[i].w;
#pragma unroll
        for (int o = 16; o > 0; o >>= 1)
            dot += __shfl_xor_sync(0xffffffffu, dot, o);

        if (lane == 0) attn_out[b * S + s] = dot;   // raw energy, normalized below

        float mn = fmaxf(m, dot);
        float scale = __expf(m - mn);
        float p = __expf(dot - mn);
        l = l * scale + p;
#pragma unroll
        for (int i = 0; i < 4; i++) {
            ctx[i].x = ctx[i].x * scale + p * ev[i].x;
            ctx[i].y = ctx[i].y * scale + p * ev[i].y;
            ctx[i].z = ctx[i].z * scale + p * ev[i].z;
            ctx[i].w = ctx[i].w * scale + p * ev[i].w;
        }
        m = mn;
    }

    __shared__ float sm_m[NWARP_ATTN];
    __shared__ float sm_l[NWARP_ATTN];
    __shared__ float sm_ctx[NWARP_ATTN][H];
#pragma unroll
    for (int i = 0; i < 4; i++)
        ((float4*)sm_ctx[warp])[lane + 32 * i] = ctx[i];
    if (lane == 0) { sm_m[warp] = m; sm_l[warp] = l; }
    __syncthreads();

    int t = threadIdx.x;  // h index
    float mg = -1e30f;
#pragma unroll
    for (int w = 0; w < NWARP_ATTN; w++) mg = fmaxf(mg, sm_m[w]);
    float lg = 0.f, c = 0.f;
#pragma unroll
    for (int w = 0; w < NWARP_ATTN; w++) {
        float sc = __expf(sm_m[w] - mg);
        lg += sc * sm_l[w];
        c += sc * sm_ctx[w][t];
    }
    float inv = 1.f / lg;
    g_hcat[b * 1024 + 512 + t] = c * inv;

    for (int s = threadIdx.x; s < S; s += 512)
        attn_out[b * S + s] = __expf(attn_out[b * S + s] - mg) * inv;
}

// ---------------- launch ----------------
extern "C" void kernel_launch(void* const* d_in, const int* in_sizes, int n_in,
                              void* d_out, int out_size) {
    const int*   idx  = (const int*)  d_in[0];
    const float* h0   = (const float*)d_in[1];
    const float* enc  = (const float*)d_in[2];
    const float* emb  = (const float*)d_in[3];
    const float* wih  = (const float*)d_in[4];
    const float* whh  = (const float*)d_in[5];
    const float* bih  = (const float*)d_in[6];
    const float* bhh  = (const float*)d_in[7];
    const float* Wc   = (const float*)d_in[8];
    const float* bc   = (const float*)d_in[9];
    const float* Wout = (const float*)d_in[10];
    const float* bout = (const float*)d_in[11];

    float* out_logits = (float*)d_out;                 // B*V
    float* out_h      = out_logits + (size_t)B * V;    // B*H
    float* out_attn   = out_h + (size_t)B * H;         // B*S

    float* gp_p; cudaGetSymbolAddress((void**)&gp_p, g_gpart);
    float* cp_p; cudaGetSymbolAddress((void**)&cp_p, g_cpart);
    float* hc_p; cudaGetSymbolAddress((void**)&hc_p, g_hcat);
    float* cc_p; cudaGetSymbolAddress((void**)&cc_p, g_concat);

    cudaFuncSetAttribute(k_gemm, cudaFuncAttributeMaxDynamicSharedMemorySize, GEMM_SMEM);

    // 1) GRU gate GEMMs (split-K x4): partials into g_gpart
    k_gemm<<<dim3(G / 128, 2, CH_G), 256, GEMM_SMEM>>>(
        emb, h0, idx, (const int*)nullptr,
        wih, whh, (const float*)nullptr, (const float*)nullptr,
        gp_p, gp_p + (size_t)CH_G * B * G,
        H, G, 0, (H / KT) / CH_G, 1);
    // 2) GRU elementwise + gates reduction
    k_gru<<<(B * H) / 256, 256>>>(h0, bih, bhh, out_h);
    // 3) fused attention
    k_attn<<<B, 512>>>(enc, out_attn);
    // 4) concat GEMM (split-K x8): partials into g_cpart
    k_gemm<<<dim3(H / 128, 1, CH_C), 256, GEMM_SMEM>>>(
        hc_p, hc_p, (const int*)nullptr, (const int*)nullptr,
        Wc, Wc, (const float*)nullptr, (const float*)nullptr,
        cp_p, cp_p,
        1024, H, 0, (1024 / KT) / CH_C, 1);
    // 5) concat reduction + tanh
    k_cfin<<<(B * H) / 256, 256>>>(bc);
    // 6) output GEMM (no split)
    k_gemm<<<dim3(V / 128, 1, 1), 256, GEMM_SMEM>>>(
        cc_p, cc_p, (const int*)nullptr, (const int*)nullptr,
        Wout, Wout, bout, bout, out_logits, out_logits,
        H, V, 0, H / KT, 0);
}

// round 6
// speedup vs baseline: 1.8812x; 1.0605x over previous
#include <cuda_runtime.h>
#include <cuda_bf16.h>
#include <cstdint>
#include <math.h>

// Problem dims
#define B 128
#define S 2048
#define H 512
#define V 32000
#define G 1536            // 3*H
#define NWARP_ATTN 16
#define CH_G 4            // k-split chunks for gates GEMM (K=512 -> 2 tiles/chunk)
#define CH_C 16           // k-split chunks for concat GEMM (K=1024 -> 1 tile/chunk)

// ---------------- scratch (no allocs allowed) ----------------
__device__ float g_gpart[2 * CH_G * B * G];   // gates partials [set][chunk][b][j]
__device__ float g_cpart[CH_C * B * H];       // concat partials [chunk][b][j]
__device__ float g_hcat[B * 1024];            // [h_new | context] per row
__device__ __nv_bfloat16 g_ch[B * H];         // concat_out hi (bf16)
__device__ __nv_bfloat16 g_cl[B * H];         // concat_out lo (bf16)

// =================== HMMA GEMM: C = A @ W^T (+bias) ===================
// 3-term bf16 split: A*W ~= Ah*Wh + Ah*Wl + Al*Wh.
// CTA tile 128(M) x 128(N), K-tile 64. 8 warps: 2(M) x 4(N), warp tile 64x32.
// Fragments via ldmatrix.x4. blockIdx.z = k-chunk (split-K when partial).

#define KT 64
#define ASTRIDE 72                       // bf16/row in smem (64+8 pad); row stride 144B
#define TILE_ELEMS (128 * ASTRIDE)       // 9216
#define GEMM_SMEM (4 * TILE_ELEMS * 2)   // Ah, Al, Wh, Wl (73728 B)

__device__ __forceinline__ uint32_t smem_u32(const void* p) {
    uint32_t a;
    asm("{ .reg .u64 t; cvta.to.shared.u64 t, %1; cvt.u32.u64 %0, t; }" : "=r"(a) : "l"(p));
    return a;
}
#define LDM4(r, addr)                                                                 \
    asm volatile("ldmatrix.sync.aligned.m8n8.x4.shared.b16 {%0,%1,%2,%3}, [%4];"      \
        : "=r"((r)[0]), "=r"((r)[1]), "=r"((r)[2]), "=r"((r)[3]) : "r"(addr))

__device__ __forceinline__ void mma16816(float* c, const uint32_t* a, const uint32_t* b) {
    asm volatile(
        "mma.sync.aligned.m16n8k16.row.col.f32.bf16.bf16.f32 "
        "{%0,%1,%2,%3}, {%4,%5,%6,%7}, {%8,%9}, {%0,%1,%2,%3};"
        : "+f"(c[0]), "+f"(c[1]), "+f"(c[2]), "+f"(c[3])
        : "r"(a[0]), "r"(a[1]), "r"(a[2]), "r"(a[3]), "r"(b[0]), "r"(b[1]));
}

__device__ __forceinline__ void cvt_store4(__nv_bfloat16* hi, __nv_bfloat16* lo,
                                           int base, float4 v) {
    float f[4] = {v.x, v.y, v.z, v.w};
#pragma unroll
    for (int p = 0; p < 2; p++) {
        float a0 = f[2 * p], a1 = f[2 * p + 1];
        __nv_bfloat16 h0 = __float2bfloat16(a0);
        __nv_bfloat16 h1 = __float2bfloat16(a1);
        __nv_bfloat16 l0 = __float2bfloat16(a0 - __bfloat162float(h0));
        __nv_bfloat16 l1 = __float2bfloat16(a1 - __bfloat162float(h1));
        __nv_bfloat162 th; th.x = h0; th.y = h1;
        __nv_bfloat162 tl; tl.x = l0; tl.y = l1;
        *(__nv_bfloat162*)(hi + base + 2 * p) = th;
        *(__nv_bfloat162*)(lo + base + 2 * p) = tl;
    }
}

template <bool ABF16>
__global__ __launch_bounds__(256, 1) void k_gemm(
    const float* Aa, const float* Ab, const int* gia, const int* gib,
    const __nv_bfloat16* Agh, const __nv_bfloat16* Agl,
    const float* Wa, const float* Wb, const float* ba_, const float* bb_,
    float* Ca, float* Cb, int K, int ldc,
    int tilesPerChunk, int partial) {
    extern __shared__ char smc[];
    __nv_bfloat16* Ahs = (__nv_bfloat16*)smc;
    __nv_bfloat16* Als = Ahs + TILE_ELEMS;
    __nv_bfloat16* Whs = Ahs + 2 * TILE_ELEMS;
    __nv_bfloat16* Wls = Ahs + 3 * TILE_ELEMS;

    int tid = threadIdx.x;
    int wid = tid >> 5;
    int lane = tid & 31;
    int wm = (wid >> 2) * 64;
    int wn = (wid & 3) * 32;

    int set = blockIdx.y;
    const float* A = set ? Ab : Aa;
    const int* gidx = set ? gib : gia;
    const float* W = set ? Wb : Wa;
    const float* bias = set ? bb_ : ba_;
    float* C = set ? Cb : Ca;
    if (partial) C += (size_t)blockIdx.z * 128 * ldc;

    int n0 = blockIdx.x * 128;
    int ktBase = blockIdx.z * tilesPerChunk;

    // ldmatrix lane base addresses (bytes, shared space)
    uint32_t sb = smem_u32(smc);
    uint32_t aLane = (uint32_t)(((lane & 7) + ((lane >> 3) & 1) * 8 + wm) * ASTRIDE +
                               (lane >> 4) * 8) * 2;
    uint32_t wLane = (uint32_t)(((lane & 7) + ((lane >> 3) >> 1) * 8 + wn) * ASTRIDE +
                               ((lane >> 3) & 1) * 8) * 2;
    uint32_t aH = sb + aLane;
    uint32_t aL = aH + TILE_ELEMS * 2;
    uint32_t wH = sb + 2 * TILE_ELEMS * 2 + wLane;
    uint32_t wL = wH + TILE_ELEMS * 2;

    // W load coords: 8 float4 per thread per tile
    int wrow[8], wkq[8];
#pragma unroll
    for (int ii = 0; ii < 8; ii++) {
        int q = tid + ii * 256;
        wrow[ii] = q >> 4;
        wkq[ii] = (q & 15) << 2;
    }
    // A (fp32 path): same coords. A (bf16 path): 4 uint4 (8 bf16 each) per plane:
    // 128 rows x 64 elems = 1024 uint4s over 256 threads.
    int arow4[4], ac4[4], larow[8];
    if (ABF16) {
#pragma unroll
        for (int ii = 0; ii < 4; ii++) {
            int q = tid + ii * 256;          // 0..1023
            arow4[ii] = q >> 3;              // 0..127
            ac4[ii] = (q & 7) << 3;          // 0,8,...,56
        }
    } else {
#pragma unroll
        for (int ii = 0; ii < 8; ii++)
            larow[ii] = gidx ? gidx[wrow[ii]] : wrow[ii];
    }

    float acc[4][4][4];
#pragma unroll
    for (int i = 0; i < 4; i++)
#pragma unroll
        for (int j = 0; j < 4; j++)
#pragma unroll
            for (int c = 0; c < 4; c++) acc[i][j][c] = 0.f;

    // prologue prefetch
    float4 pw[8], pa[8];
    uint4 ph[4], pl[4];
    {
        int k0 = ktBase * KT;
#pragma unroll
        for (int ii = 0; ii < 8; ii++)
            pw[ii] = *(const float4*)(W + (size_t)(n0 + wrow[ii]) * K + k0 + wkq[ii]);
        if (ABF16) {
#pragma unroll
            for (int ii = 0; ii < 4; ii++) {
                size_t g = (size_t)arow4[ii] * K + k0 + ac4[ii];
                ph[ii] = *(const uint4*)(Agh + g);
                pl[ii] = *(const uint4*)(Agl + g);
            }
        } else {
#pragma unroll
            for (int ii = 0; ii < 8; ii++)
                pa[ii] = *(const float4*)(A + (size_t)larow[ii] * K + k0 + wkq[ii]);
        }
    }

    for (int kt = 0; kt < tilesPerChunk; kt++) {
        // commit prefetched tile
#pragma unroll
        for (int ii = 0; ii < 8; ii++)
            cvt_store4(Whs, Wls, wrow[ii] * ASTRIDE + wkq[ii], pw[ii]);
        if (ABF16) {
#pragma unroll
            for (int ii = 0; ii < 4; ii++) {
                int base = arow4[ii] * ASTRIDE + ac4[ii];
                *(uint4*)(Ahs + base) = ph[ii];
                *(uint4*)(Als + base) = pl[ii];
            }
        } else {
#pragma unroll
            for (int ii = 0; ii < 8; ii++)
                cvt_store4(Ahs, Als, wrow[ii] * ASTRIDE + wkq[ii], pa[ii]);
        }
        __syncthreads();

        // prefetch next tile (overlaps MMA)
        if (kt + 1 < tilesPerChunk) {
            int k0 = (ktBase + kt + 1) * KT;
#pragma unroll
            for (int ii = 0; ii < 8; ii++)
                pw[ii] = *(const float4*)(W + (size_t)(n0 + wrow[ii]) * K + k0 + wkq[ii]);
            if (ABF16) {
#pragma unroll
                for (int ii = 0; ii < 4; ii++) {
                    size_t g = (size_t)arow4[ii] * K + k0 + ac4[ii];
                    ph[ii] = *(const uint4*)(Agh + g);
                    pl[ii] = *(const uint4*)(Agl + g);
                }
            } else {
#pragma unroll
                for (int ii = 0; ii < 8; ii++)
                    pa[ii] = *(const float4*)(A + (size_t)larow[ii] * K + k0 + wkq[ii]);
            }
        }

#pragma unroll
        for (int ks = 0; ks < 4; ks++) {
            uint32_t kso = ks * 32;   // 16 bf16 = 32 bytes
            uint32_t ah[4][4], al[4][4], wf[2][4], wg[2][4];
#pragma unroll
            for (int mt = 0; mt < 4; mt++) {
                LDM4(ah[mt], aH + mt * (16 * ASTRIDE * 2) + kso);
                LDM4(al[mt], aL + mt * (16 * ASTRIDE * 2) + kso);
            }
#pragma unroll
            for (int p = 0; p < 2; p++) {
                LDM4(wf[p], wH + p * (16 * ASTRIDE * 2) + kso);
                LDM4(wg[p], wL + p * (16 * ASTRIDE * 2) + kso);
            }
#pragma unroll
            for (int mt = 0; mt < 4; mt++)
#pragma unroll
                for (int nt = 0; nt < 4; nt++) {
                    const uint32_t* bh = &wf[nt >> 1][(nt & 1) * 2];
                    const uint32_t* bl = &wg[nt >> 1][(nt & 1) * 2];
                    mma16816(acc[mt][nt], ah[mt], bh);
                    mma16816(acc[mt][nt], ah[mt], bl);
                    mma16816(acc[mt][nt], al[mt], bh);
                }
        }
        __syncthreads();
    }

    // ---- epilogue ----
#pragma unroll
    for (int mt = 0; mt < 4; mt++) {
        int r0 = wm + mt * 16 + (lane >> 2);
#pragma unroll
        for (int nt = 0; nt < 4; nt++) {
            int col = n0 + wn + nt * 8 + (lane & 3) * 2;
            float v0 = acc[mt][nt][0];
            float v1 = acc[mt][nt][1];
            float v2 = acc[mt][nt][2];
            float v3 = acc[mt][nt][3];
            if (!partial) {
                float b0 = bias[col], b1 = bias[col + 1];
                v0 += b0; v1 += b1; v2 += b0; v3 += b1;
            }
            *(float2*)(C + (size_t)r0 * ldc + col) = make_float2(v0, v1);
            *(float2*)(C + (size_t)(r0 + 8) * ldc + col) = make_float2(v2, v3);
        }
    }
}

// ---------------- GRU elementwise + gates split-K reduction ----------------
__global__ void k_gru(const float* __restrict__ h0,
                      const float* __restrict__ bih, const float* __restrict__ bhh,
                      float* __restrict__ out_h) {
    int t = blockIdx.x * blockDim.x + threadIdx.x;   // t < B*H
    int b = t >> 9;
    int hh = t & (H - 1);
    float gir = bih[hh],  giz = bih[H + hh],  gin = bih[2 * H + hh];
    float ghr = bhh[hh],  ghz = bhh[H + hh],  ghn = bhh[2 * H + hh];
#pragma unroll
    for (int c = 0; c < CH_G; c++) {
        const float* p = g_gpart + ((size_t)c * B + b) * G;
        gir += p[hh]; giz += p[H + hh]; gin += p[2 * H + hh];
        const float* q = g_gpart + ((size_t)(CH_G + c) * B + b) * G;
        ghr += q[hh]; ghz += q[H + hh]; ghn += q[2 * H + hh];
    }
    float r = 1.f / (1.f + __expf(-(gir + ghr)));
    float z = 1.f / (1.f + __expf(-(giz + ghz)));
    float n = tanhf(gin + r * ghn);
    float hp = h0[t];
    float hn = (1.f - z) * n + z * hp;
    g_hcat[b * 1024 + hh] = hn;
    out_h[t] = hn;
}

// ---------------- concat split-K reduction + bias + tanh + bf16 split ----------------
__global__ void k_cfin(const float* __restrict__ bc) {
    int t = blockIdx.x * blockDim.x + threadIdx.x;   // t < B*H
    int b = t >> 9;
    int j = t & (H - 1);
    float sum = bc[j];
#pragma unroll
    for (int c = 0; c < CH_C; c++)
        sum += g_cpart[((size_t)c * B + b) * H + j];
    float v = tanhf(sum);
    __nv_bfloat16 h = __float2bfloat16(v);
    g_ch[t] = h;
    g_cl[t] = __float2bfloat16(v - __bfloat162float(h));
}

// ---------------- fused energies + online softmax + context + normalize ----------------
__global__ __launch_bounds__(512, 1) void k_attn(const float* __restrict__ enc,
                                                 float* __restrict__ attn_out) {
    int b = blockIdx.x;
    int lane = threadIdx.x & 31;
    int warp = threadIdx.x >> 5;

    const float4* hrow = (const float4*)(g_hcat + b * 1024);
    float4 hreg[4];
#pragma unroll
    for (int i = 0; i < 4; i++) hreg[i] = hrow[lane + 32 * i];

    float m = -1e30f, l = 0.f;
    float4 ctx[4];
#pragma unroll
    for (int i = 0; i < 4; i++) ctx[i] = make_float4(0.f, 0.f, 0.f, 0.f);

    const float* encb = enc + (size_t)b * S * H;
    for (int s = warp; s < S; s += NWARP_ATTN) {
        const float4* er = (const float4*)(encb + (size_t)s * H);
        float4 ev[4];
#pragma unroll
        for (int i = 0; i < 4; i++) ev[i] = er[lane + 32 * i];
        float dot = 0.f;
#pragma unroll
        for (int i = 0; i < 4; i++)
            dot += hreg[i].x * ev[i].x + hreg[i].y * ev[i].y +
                   hreg[i].z * ev[i].z + hreg[i].w * ev[i].w;
#pragma unroll
        for (int o = 16; o > 0; o >>= 1)
            dot += __shfl_xor_sync(0xffffffffu, dot, o);

        if (lane == 0) attn_out[b * S + s] = dot;   // raw energy, normalized below

        float mn = fmaxf(m, dot);
        float scale = __expf(m - mn);
        float p = __expf(dot - mn);
        l = l * scale + p;
#pragma unroll
        for (int i = 0; i < 4; i++) {
            ctx[i].x = ctx[i].x * scale + p * ev[i].x;
            ctx[i].y = ctx[i].y * scale + p * ev[i].y;
            ctx[i].z = ctx[i].z * scale + p * ev[i].z;
            ctx[i].w = ctx[i].w * scale + p * ev[i].w;
        }
        m = mn;
    }

    __shared__ float sm_m[NWARP_ATTN];
    __shared__ float sm_l[NWARP_ATTN];
    __shared__ float sm_ctx[NWARP_ATTN][H];
#pragma unroll
    for (int i = 0; i < 4; i++)
        ((float4*)sm_ctx[warp])[lane + 32 * i] = ctx[i];
    if (lane == 0) { sm_m[warp] = m; sm_l[warp] = l; }
    __syncthreads();

    int t = threadIdx.x;  // h index
    float mg = -1e30f;
#pragma unroll
    for (int w = 0; w < NWARP_ATTN; w++) mg = fmaxf(mg, sm_m[w]);
    float lg = 0.f, c = 0.f;
#pragma unroll
    for (int w = 0; w < NWARP_ATTN; w++) {
        float sc = __expf(sm_m[w] - mg);
        lg += sc * sm_l[w];
        c += sc * sm_ctx[w][t];
    }
    float inv = 1.f / lg;
    g_hcat[b * 1024 + 512 + t] = c * inv;

    for (int s = threadIdx.x; s < S; s += 512)
        attn_out[b * S + s] = __expf(attn_out[b * S + s] - mg) * inv;
}

// ---------------- launch ----------------
extern "C" void kernel_launch(void* const* d_in, const int* in_sizes, int n_in,
                              void* d_out, int out_size) {
    const int*   idx  = (const int*)  d_in[0];
    const float* h0   = (const float*)d_in[1];
    const float* enc  = (const float*)d_in[2];
    const float* emb  = (const float*)d_in[3];
    const float* wih  = (const float*)d_in[4];
    const float* whh  = (const float*)d_in[5];
    const float* bih  = (const float*)d_in[6];
    const float* bhh  = (const float*)d_in[7];
    const float* Wc   = (const float*)d_in[8];
    const float* bc   = (const float*)d_in[9];
    const float* Wout = (const float*)d_in[10];
    const float* bout = (const float*)d_in[11];

    float* out_logits = (float*)d_out;                 // B*V
    float* out_h      = out_logits + (size_t)B * V;    // B*H
    float* out_attn   = out_h + (size_t)B * H;         // B*S

    float* gp_p; cudaGetSymbolAddress((void**)&gp_p, g_gpart);
    float* cp_p; cudaGetSymbolAddress((void**)&cp_p, g_cpart);
    float* hc_p; cudaGetSymbolAddress((void**)&hc_p, g_hcat);
    __nv_bfloat16* ch_p; cudaGetSymbolAddress((void**)&ch_p, g_ch);
    __nv_bfloat16* cl_p; cudaGetSymbolAddress((void**)&cl_p, g_cl);

    cudaFuncSetAttribute(k_gemm<false>, cudaFuncAttributeMaxDynamicSharedMemorySize, GEMM_SMEM);
    cudaFuncSetAttribute(k_gemm<true>, cudaFuncAttributeMaxDynamicSharedMemorySize, GEMM_SMEM);

    // 1) GRU gate GEMMs (split-K x4): partials into g_gpart
    k_gemm<false><<<dim3(G / 128, 2, CH_G), 256, GEMM_SMEM>>>(
        emb, h0, idx, (const int*)nullptr,
        (const __nv_bfloat16*)nullptr, (const __nv_bfloat16*)nullptr,
        wih, whh, (const float*)nullptr, (const float*)nullptr,
        gp_p, gp_p + (size_t)CH_G * B * G,
        H, G, (H / KT) / CH_G, 1);
    // 2) GRU elementwise + gates reduction
    k_gru<<<(B * H) / 256, 256>>>(h0, bih, bhh, out_h);
    // 3) fused attention
    k_attn<<<B, 512>>>(enc, out_attn);
    // 4) concat GEMM (split-K x16): partials into g_cpart
    k_gemm<false><<<dim3(H / 128, 1, CH_C), 256, GEMM_SMEM>>>(
        hc_p, hc_p, (const int*)nullptr, (const int*)nullptr,
        (const __nv_bfloat16*)nullptr, (const __nv_bfloat16*)nullptr,
        Wc, Wc, (const float*)nullptr, (const float*)nullptr,
        cp_p, cp_p,
        1024, H, (1024 / KT) / CH_C, 1);
    // 5) concat reduction + tanh + bf16 hi/lo split
    k_cfin<<<(B * H) / 256, 256>>>(bc);
    // 6) output GEMM (A pre-split bf16)
    k_gemm<true><<<dim3(V / 128, 1, 1), 256, GEMM_SMEM>>>(
        (const float*)nullptr, (const float*)nullptr, (const int*)nullptr, (const int*)nullptr,
        ch_p, cl_p,
        Wout, Wout, bout, bout, out_logits, out_logits,
        H, V, H / KT, 0);
}